// round 7
// baseline (speedup 1.0000x reference)
#include <cuda_runtime.h>
#include <math.h>

// ---------------- problem constants ----------------
#define BB 4
#define SS 512
#define DD 768
#define FF_ 3072
#define VV 30000
#define HH 12
#define MM 64
#define DH 64
#define NLAYERS 12

// ---------------- static device scratch ----------------
__device__ float g_x [BB*SS*DD];
__device__ float g_y [BB*SS*DD];
__device__ float g_q [BB*SS*DD];
__device__ float g_k [BB*SS*DD];
__device__ float g_v [BB*SS*DD];
__device__ float g_att[BB*HH*SS*SS];
__device__ float g_h1[BB*SS*FF_];
__device__ float g_g [BB*MM*DD];
__device__ int   g_tok[BB*SS];

// ---------------- epilogue flags ----------------
#define EPI_BIAS  1
#define EPI_RELU  2
#define EPI_RESID 4

// ======================================================================
// Tiled fp32 GEMM: C[z] = scale * A[z] @ op(B[z]) (+bias)(+relu)(+resid)
// BM=128, BN=64, BK=16, 256 threads, 8x4 micro-tile per thread.
// Batched via blockIdx.z decomposed as (zb, zh) with independent strides.
// Assumes: M % 128 == 0, K % 16 == 0, lda/ldb/ldc and base offsets % 4 == 0.
// N may be ragged (guarded).  TRANS_B path assumes N % 64 == 0 (true here).
// ======================================================================
template<int EPI, bool TB>
__global__ void __launch_bounds__(256)
gemm_k(const float* __restrict__ A, const float* __restrict__ B,
       float* __restrict__ C, const float* __restrict__ bias,
       const float* __restrict__ resid,
       int M, int N, int K, int lda, int ldb, int ldc, float scale,
       int batchH, long long sAb, long long sAh, long long sBb, long long sBh,
       long long sCb, long long sCh)
{
    constexpr int BM = 128, BN = 64, BK = 16;
    __shared__ float As[BK][BM];
    __shared__ float Bs[BK][BN];

    int z  = blockIdx.z;
    int zb = z / batchH;
    int zh = z - zb * batchH;
    A += zb * sAb + zh * sAh;
    B += zb * sBb + zh * sBh;
    long long coff = zb * sCb + zh * sCh;
    C += coff;
    if (EPI & EPI_RESID) resid += coff;

    const int m0  = blockIdx.y * BM;
    const int n0  = blockIdx.x * BN;
    const int tid = threadIdx.x;
    const int tx  = tid & 15;
    const int ty  = tid >> 4;

    // A-tile load mapping: 256 threads, each loads 8 consecutive k (2 x float4)
    const int ar = tid >> 1;          // 0..127 (row within tile)
    const int ak = (tid & 1) * 8;     // 0 or 8

    // B-tile load mapping
    int bk, bn;
    if (TB) { bn = tid >> 2; bk = (tid & 3) * 4; }   // B is [N,K]
    else    { bk = tid >> 4; bn = (tid & 15) * 4; }  // B is [K,N]

    float acc[8][4];
#pragma unroll
    for (int i = 0; i < 8; i++)
#pragma unroll
        for (int j = 0; j < 4; j++) acc[i][j] = 0.f;

    for (int k0 = 0; k0 < K; k0 += BK) {
        // ---- load A tile (always in range: M%128==0, K%16==0) ----
        {
            const float* Ap = A + (size_t)(m0 + ar) * lda + (k0 + ak);
            float4 a0 = *(const float4*)Ap;
            float4 a1 = *(const float4*)(Ap + 4);
            As[ak + 0][ar] = a0.x; As[ak + 1][ar] = a0.y;
            As[ak + 2][ar] = a0.z; As[ak + 3][ar] = a0.w;
            As[ak + 4][ar] = a1.x; As[ak + 5][ar] = a1.y;
            As[ak + 6][ar] = a1.z; As[ak + 7][ar] = a1.w;
        }
        // ---- load B tile ----
        if (TB) {
            const float* Bp = B + (size_t)(n0 + bn) * ldb + (k0 + bk);
            float4 b4 = *(const float4*)Bp;
            Bs[bk + 0][bn] = b4.x; Bs[bk + 1][bn] = b4.y;
            Bs[bk + 2][bn] = b4.z; Bs[bk + 3][bn] = b4.w;
        } else {
            int n = n0 + bn;
            float4 b4;
            if (n + 3 < N) {
                b4 = *(const float4*)(B + (size_t)(k0 + bk) * ldb + n);
            } else {
                float t0 = (n + 0 < N) ? B[(size_t)(k0 + bk) * ldb + n + 0] : 0.f;
                float t1 = (n + 1 < N) ? B[(size_t)(k0 + bk) * ldb + n + 1] : 0.f;
                float t2 = (n + 2 < N) ? B[(size_t)(k0 + bk) * ldb + n + 2] : 0.f;
                float t3 = (n + 3 < N) ? B[(size_t)(k0 + bk) * ldb + n + 3] : 0.f;
                b4 = make_float4(t0, t1, t2, t3);
            }
            *(float4*)&Bs[bk][bn] = b4;
        }
        __syncthreads();

#pragma unroll
        for (int kk = 0; kk < BK; kk++) {
            float4 a0 = *(const float4*)&As[kk][ty * 8];
            float4 a1 = *(const float4*)&As[kk][ty * 8 + 4];
            float4 bv = *(const float4*)&Bs[kk][tx * 4];
            float a[8] = {a0.x, a0.y, a0.z, a0.w, a1.x, a1.y, a1.z, a1.w};
            float b[4] = {bv.x, bv.y, bv.z, bv.w};
#pragma unroll
            for (int i = 0; i < 8; i++)
#pragma unroll
                for (int j = 0; j < 4; j++)
                    acc[i][j] = fmaf(a[i], b[j], acc[i][j]);
        }
        __syncthreads();
    }

    // ---- epilogue ----
    const int cm = m0 + ty * 8;
    const int cn = n0 + tx * 4;
    float bvv[4] = {0.f, 0.f, 0.f, 0.f};
    if (EPI & EPI_BIAS) {
#pragma unroll
        for (int j = 0; j < 4; j++)
            if (cn + j < N) bvv[j] = bias[cn + j];
    }
#pragma unroll
    for (int i = 0; i < 8; i++) {
        int r = cm + i;
#pragma unroll
        for (int j = 0; j < 4; j++) {
            int c = cn + j;
            if (c < N) {
                float v = acc[i][j] * scale;
                if (EPI & EPI_BIAS)  v += bvv[j];
                if (EPI & EPI_RELU)  v = fmaxf(v, 0.f);
                if (EPI & EPI_RESID) v += resid[(size_t)r * ldc + c];
                C[(size_t)r * ldc + c] = v;
            }
        }
    }
}

// ======================================================================
// one-hot -> token id (each row has exactly one 1.0)
// ======================================================================
__global__ void findtok_k(const float* __restrict__ oh, int* __restrict__ tok)
{
    size_t row = blockIdx.x;
    const float* r = oh + row * (size_t)VV;
    for (int j = threadIdx.x; j < VV; j += blockDim.x)
        if (r[j] > 0.5f) tok[row] = j;
}

// ======================================================================
// x = se_w[tok] + se_b + positional encoding
// pe[s,d]: raw = s / 10000^(2d/D); s==0 -> 0; else sin(raw) for even d,
// cos(raw) for odd d (matches reference exactly incl. per-column exponent).
// ======================================================================
__global__ void embed_k(const float* __restrict__ se_w, const float* __restrict__ se_b,
                        const int* __restrict__ tok, float* __restrict__ x)
{
    int row = blockIdx.x;           // b*S + s
    int s   = row & (SS - 1);
    int tk  = tok[row];
    const float* wrow = se_w + (size_t)tk * DD;
    float* xr = x + (size_t)row * DD;
    for (int d = threadIdx.x; d < DD; d += blockDim.x) {
        float pe = 0.f;
        if (s != 0) {
            float denom = powf(10000.0f, (2.0f * (float)d) / (float)DD);
            float raw   = (float)s / denom;
            pe = (d & 1) ? cosf(raw) : sinf(raw);
        }
        xr[d] = wrow[d] + se_b[d] + pe;
    }
}

// ======================================================================
// row softmax over 512 (one block per row, 256 threads, float2 per thread)
// ======================================================================
__global__ void softmax_k(float* __restrict__ att)
{
    __shared__ float red[8];
    size_t row = blockIdx.x;
    float2* p = reinterpret_cast<float2*>(att) + row * 256;
    int t = threadIdx.x;
    float2 v = p[t];
    float m = fmaxf(v.x, v.y);
#pragma unroll
    for (int o = 16; o; o >>= 1) m = fmaxf(m, __shfl_xor_sync(0xffffffffu, m, o));
    if ((t & 31) == 0) red[t >> 5] = m;
    __syncthreads();
    m = fmaxf(fmaxf(fmaxf(red[0], red[1]), fmaxf(red[2], red[3])),
              fmaxf(fmaxf(red[4], red[5]), fmaxf(red[6], red[7])));
    float ex = expf(v.x - m), ey = expf(v.y - m);
    float s = ex + ey;
#pragma unroll
    for (int o = 16; o; o >>= 1) s += __shfl_xor_sync(0xffffffffu, s, o);
    __syncthreads();
    if ((t & 31) == 0) red[t >> 5] = s;
    __syncthreads();
    s = red[0] + red[1] + red[2] + red[3] + red[4] + red[5] + red[6] + red[7];
    float inv = 1.0f / s;
    p[t] = make_float2(ex * inv, ey * inv);
}

// ======================================================================
// layernorm over D=768 (block per row, 256 threads, 3 elems each)
// ======================================================================
__global__ void layernorm_k(const float* __restrict__ y, float* __restrict__ x)
{
    __shared__ float rs[8], rq[8];
    size_t row = blockIdx.x;
    const float* yp = y + row * DD;
    float* xp = x + row * DD;
    int t = threadIdx.x;
    float a0 = yp[t], a1 = yp[t + 256], a2 = yp[t + 512];
    float s = a0 + a1 + a2;
    float q = a0 * a0 + a1 * a1 + a2 * a2;
#pragma unroll
    for (int o = 16; o; o >>= 1) {
        s += __shfl_xor_sync(0xffffffffu, s, o);
        q += __shfl_xor_sync(0xffffffffu, q, o);
    }
    if ((t & 31) == 0) { rs[t >> 5] = s; rq[t >> 5] = q; }
    __syncthreads();
    s = rs[0] + rs[1] + rs[2] + rs[3] + rs[4] + rs[5] + rs[6] + rs[7];
    q = rq[0] + rq[1] + rq[2] + rq[3] + rq[4] + rq[5] + rq[6] + rq[7];
    float mean = s * (1.0f / (float)DD);
    float var  = q * (1.0f / (float)DD) - mean * mean;
    float r = rsqrtf(var + 1e-5f);
    xp[t]       = (a0 - mean) * r;
    xp[t + 256] = (a1 - mean) * r;
    xp[t + 512] = (a2 - mean) * r;
}

// ======================================================================
// gather masked rows: g[b*M+m, :] = x[b*S + idx[b,m], :]
// ======================================================================
__global__ void gather_k(const float* __restrict__ x, const int* __restrict__ idx,
                         float* __restrict__ g)
{
    int r = blockIdx.x;         // 0..B*M-1
    int b = r >> 6;             // M == 64
    int s = idx[r];
    const float* src = x + ((size_t)(b * SS + s)) * DD;
    float* dst = g + (size_t)r * DD;
    for (int d = threadIdx.x; d < DD; d += blockDim.x) dst[d] = src[d];
}

// ======================================================================
// in-place log_softmax over V=30000 (block per row)
// ======================================================================
__global__ void logsoftmax_k(float* __restrict__ out)
{
    __shared__ float red[8];
    size_t row = blockIdx.x;
    float* p = out + row * (size_t)VV;
    int t = threadIdx.x;

    float m = -1e30f;
    for (int j = t; j < VV; j += 256) m = fmaxf(m, p[j]);
#pragma unroll
    for (int o = 16; o; o >>= 1) m = fmaxf(m, __shfl_xor_sync(0xffffffffu, m, o));
    if ((t & 31) == 0) red[t >> 5] = m;
    __syncthreads();
    m = fmaxf(fmaxf(fmaxf(red[0], red[1]), fmaxf(red[2], red[3])),
              fmaxf(fmaxf(red[4], red[5]), fmaxf(red[6], red[7])));

    float s = 0.f;
    for (int j = t; j < VV; j += 256) s += expf(p[j] - m);
#pragma unroll
    for (int o = 16; o; o >>= 1) s += __shfl_xor_sync(0xffffffffu, s, o);
    __syncthreads();
    if ((t & 31) == 0) red[t >> 5] = s;
    __syncthreads();
    s = red[0] + red[1] + red[2] + red[3] + red[4] + red[5] + red[6] + red[7];

    float lse = m + logf(s);
    for (int j = t; j < VV; j += 256) p[j] = p[j] - lse;
}

// ======================================================================
// launcher
// ======================================================================
extern "C" void kernel_launch(void* const* d_in, const int* in_sizes, int n_in,
                              void* d_out, int out_size)
{
    (void)in_sizes; (void)n_in; (void)out_size;
    const float* onehot = (const float*)d_in[0];
    const float* se_w = (const float*)d_in[1];
    const float* se_b = (const float*)d_in[2];
    const float* wq = (const float*)d_in[3];  const float* bq = (const float*)d_in[4];
    const float* wk = (const float*)d_in[5];  const float* bk = (const float*)d_in[6];
    const float* wv = (const float*)d_in[7];  const float* bv = (const float*)d_in[8];
    const float* wo = (const float*)d_in[9];  const float* bo = (const float*)d_in[10];
    const float* w1 = (const float*)d_in[11]; const float* b1 = (const float*)d_in[12];
    const float* w2 = (const float*)d_in[13]; const float* b2 = (const float*)d_in[14];
    const float* we = (const float*)d_in[15]; const float* be = (const float*)d_in[16];
    const int*   idx = (const int*)d_in[17];
    float* out = (float*)d_out;

    // resolve device-global scratch addresses (pure lookups, capture-safe)
    float *px, *py, *pq, *pk, *pv, *patt, *ph1, *pg; int* ptok;
    cudaGetSymbolAddress((void**)&px,   g_x);
    cudaGetSymbolAddress((void**)&py,   g_y);
    cudaGetSymbolAddress((void**)&pq,   g_q);
    cudaGetSymbolAddress((void**)&pk,   g_k);
    cudaGetSymbolAddress((void**)&pv,   g_v);
    cudaGetSymbolAddress((void**)&patt, g_att);
    cudaGetSymbolAddress((void**)&ph1,  g_h1);
    cudaGetSymbolAddress((void**)&pg,   g_g);
    cudaGetSymbolAddress((void**)&ptok, g_tok);

    const int Mrows = BB * SS;       // 2048
    const float scl = 0.125f;        // 1/sqrt(64)

    // ---- embedding ----
    findtok_k<<<Mrows, 256>>>(onehot, ptok);
    embed_k<<<Mrows, 256>>>(se_w, se_b, ptok, px);

    const long long sQKb = (long long)SS * DD;   // per-batch stride in q/k/v/o
    const long long sQKh = DH;                   // per-head stride
    const long long sAb  = (long long)HH * SS * SS;
    const long long sAh  = (long long)SS * SS;

    for (int l = 0; l < NLAYERS; l++) {
        // QKV projections: [2048,768] @ [768,768] + bias
        dim3 gp((DD + 63) / 64, Mrows / 128, 1);
        gemm_k<EPI_BIAS, false><<<gp, 256>>>(px, wq, pq, bq, nullptr,
            Mrows, DD, DD, DD, DD, DD, 1.f, 1, 0, 0, 0, 0, 0, 0);
        gemm_k<EPI_BIAS, false><<<gp, 256>>>(px, wk, pk, bk, nullptr,
            Mrows, DD, DD, DD, DD, DD, 1.f, 1, 0, 0, 0, 0, 0, 0);
        gemm_k<EPI_BIAS, false><<<gp, 256>>>(px, wv, pv, bv, nullptr,
            Mrows, DD, DD, DD, DD, DD, 1.f, 1, 0, 0, 0, 0, 0, 0);

        // scores: att[b,h] = scale * q[b,:,h,:] @ k[b,:,h,:]^T   (48 batches)
        dim3 gs(SS / 64, SS / 128, BB * HH);
        gemm_k<0, true><<<gs, 256>>>(pq, pk, patt, nullptr, nullptr,
            SS, SS, DH, DD, DD, SS, scl, HH, sQKb, sQKh, sQKb, sQKh, sAb, sAh);

        // softmax over last dim
        softmax_k<<<BB * HH * SS, 256>>>(patt);

        // o[b,:,h,:] = att[b,h] @ v[b,:,h,:]  (write into pq, q is dead)
        dim3 ga(1, SS / 128, BB * HH);
        gemm_k<0, false><<<ga, 256>>>(patt, pv, pq, nullptr, nullptr,
            SS, DH, SS, SS, DD, DD, 1.f, HH, sAb, sAh, sQKb, sQKh, sQKb, sQKh);

        // y = o @ wo + bo + x   (residual)
        gemm_k<EPI_BIAS | EPI_RESID, false><<<gp, 256>>>(pq, wo, py, bo, px,
            Mrows, DD, DD, DD, DD, DD, 1.f, 1, 0, 0, 0, 0, 0, 0);

        // x = layernorm(y)
        layernorm_k<<<Mrows, 256>>>(py, px);

        // h1 = relu(x @ w1 + b1)
        dim3 gf1((FF_ + 63) / 64, Mrows / 128, 1);
        gemm_k<EPI_BIAS | EPI_RELU, false><<<gf1, 256>>>(px, w1, ph1, b1, nullptr,
            Mrows, FF_, DD, DD, FF_, FF_, 1.f, 1, 0, 0, 0, 0, 0, 0);

        // x = h1 @ w2 + b2   (no residual, matches reference)
        gemm_k<EPI_BIAS, false><<<gp, 256>>>(ph1, w2, px, b2, nullptr,
            Mrows, DD, FF_, FF_, DD, DD, 1.f, 1, 0, 0, 0, 0, 0, 0);
    }

    // gather masked rows, project to vocab, log_softmax
    gather_k<<<BB * MM, 256>>>(px, idx, pg);
    dim3 ge((VV + 63) / 64, (BB * MM) / 128, 1);
    gemm_k<EPI_BIAS, false><<<ge, 256>>>(pg, we, out, be, nullptr,
        BB * MM, VV, DD, DD, VV, VV, 1.f, 1, 0, 0, 0, 0, 0, 0);
    logsoftmax_k<<<BB * MM, 256>>>(out);
}